// round 15
// baseline (speedup 1.0000x reference)
#include <cuda_runtime.h>
#include <cuda_fp16.h>
#include <cstdint>
#include <math.h>

#define NB 8192
#define ND 1024
#define BM 128                  /* CTA rows */
#define BN 256                  /* CTA cols (2 x 128-col blocks) */
#define BK 64
#define NBLK 64                 /* 128-row blocks */
#define NSUPER 32               /* 256-col superblocks */
#define NCTAS 1056              /* sum_{i=0}^{63} (32 - i/2) */
#define THREADS 256
#define LDS_PAD 72              /* halves per smem row (144B) */
#define KBLOCKS (ND / BK)       /* 16 */
#define RED_BLOCKS 32
#define NCHUNK 128              /* 64-row normalize chunks */

/* dynamic SMEM layout (bytes) */
#define A_BUF 18432             /* 128*144 */
#define B_BUF 36864             /* 256*144 */
#define OFF_B (2 * A_BUF)       /* 36864 */
#define SMEM_TOTAL (OFF_B + 2 * B_BUF)   /* 110592 */
/* epilogue scratch aliases A stage-0 (dead after kb=14) */
#define OFF_RR 0                /* s_redr [4][128] float2 = 4096 B */
#define OFF_RC 4096             /* s_redc [2][256] float2 = 4096 B */

// ---------------- static device scratch (no allocation) --------------------
__device__ __half g_h[NB * ND];             // normalized rows fp16 (16 MB)
__device__ float2 g_part[96 * NB];          // [slot][row]; 0..31 row-side (J), 32..95 col-side (i)
__device__ float2 g_red[RED_BLOCKS];
__device__ int    g_ctr;                    // static-zero; reset in-kernel
__device__ int    g_flag[NCHUNK];           // chunk-ready flags; reset in loss_kernel

// ---------------- PTX helpers ----------------------------------------------
__device__ __forceinline__ uint32_t smem_u32(const void* p) {
    uint32_t a;
    asm("{ .reg .u64 t; cvta.to.shared.u64 t, %1; cvt.u32.u64 %0, t; }" : "=r"(a) : "l"(p));
    return a;
}
#define CP_ASYNC16(sm, gp) \
    asm volatile("cp.async.cg.shared.global [%0], [%1], 16;" :: "r"(sm), "l"(gp))
#define CP_COMMIT() asm volatile("cp.async.commit_group;" ::: "memory")
#define CP_WAIT0()  asm volatile("cp.async.wait_group 0;" ::: "memory")
#define LDMATRIX_X4(r0, r1, r2, r3, addr) \
    asm volatile("ldmatrix.sync.aligned.m8n8.x4.shared.b16 {%0,%1,%2,%3}, [%4];" \
                 : "=r"(r0), "=r"(r1), "=r"(r2), "=r"(r3) : "r"(addr))
#define MMA16816H(c, a, b0, b1) \
    asm volatile("mma.sync.aligned.m16n8k16.row.col.f16.f16.f16.f16 " \
                 "{%0,%1},{%2,%3,%4,%5},{%6,%7},{%0,%1};" \
                 : "+r"((c)[0]), "+r"((c)[1]) \
                 : "r"((a)[0]), "r"((a)[1]), "r"((a)[2]), "r"((a)[3]), "r"(b0), "r"(b1))

__device__ __forceinline__ void top2_merge(float2& t, float2 q) {
    if (q.x > t.x) { t.y = fmaxf(t.x, q.y); t.x = q.x; }
    else           { t.y = fmaxf(t.y, q.x); }
}
__device__ __forceinline__ void top2_push(float2& t, float v) {
    if (v > t.x) { t.y = t.x; t.x = v; }
    else if (v > t.y) { t.y = v; }
}
__device__ __forceinline__ void top2_shfl_merge(float2& t, int off) {
    float2 q;
    q.x = __shfl_xor_sync(0xFFFFFFFFu, t.x, off);
    q.y = __shfl_xor_sync(0xFFFFFFFFu, t.y, off);
    top2_merge(t, q);
}

// ---------------------------------------------------------------------------
// Kernel 1 (fused): normalize chunk (CTAs 0..127) + symmetric fp16 GEMM +
//                   row/col top-2.  Flag-gated start.
// ---------------------------------------------------------------------------
__global__ void __launch_bounds__(THREADS, 2) top2_sym_kernel(const float* __restrict__ x) {
    extern __shared__ char smem[];
    float2* s_redr = reinterpret_cast<float2*>(smem + OFF_RR);  // [4][128]
    float2* s_redc = reinterpret_cast<float2*>(smem + OFF_RC);  // [2][256]

    const int tid = threadIdx.x;
    const int wid = tid >> 5, lane = tid & 31;
    const int bid = blockIdx.x;

    // ---- phase 0: CTAs 0..127 normalize their 64-row chunk ----
    if (bid < NCHUNK) {
        const int chunk0 = bid * 64;
        #pragma unroll 1
        for (int it = 0; it < 8; it++) {
            const int row = chunk0 + it * 8 + wid;
            const float4* xr = reinterpret_cast<const float4*>(x + (size_t)row * ND);
            float4 v[8];
            float s = 0.0f;
            #pragma unroll
            for (int q = 0; q < 8; q++) {
                v[q] = xr[lane + 32 * q];
                s += v[q].x * v[q].x + v[q].y * v[q].y + v[q].z * v[q].z + v[q].w * v[q].w;
            }
            #pragma unroll
            for (int o = 16; o > 0; o >>= 1) s += __shfl_xor_sync(0xFFFFFFFFu, s, o);
            const float inv = 1.0f / fmaxf(sqrtf(s), 1e-8f);
            uint2* oh = reinterpret_cast<uint2*>(g_h + (size_t)row * ND);
            #pragma unroll
            for (int q = 0; q < 8; q++) {
                __half2 h0 = __floats2half2_rn(v[q].x * inv, v[q].y * inv);
                __half2 h1 = __floats2half2_rn(v[q].z * inv, v[q].w * inv);
                uint2 pk;
                pk.x = *reinterpret_cast<uint32_t*>(&h0);
                pk.y = *reinterpret_cast<uint32_t*>(&h1);
                oh[lane + 32 * q] = pk;
            }
        }
        __threadfence();
        __syncthreads();
        if (tid == 0) atomicExch(&g_flag[bid], 1);
    }

    // decode (i, J): J >= i/2
    int i = 0, rem = bid;
    while (rem >= NSUPER - (i >> 1)) { rem -= NSUPER - (i >> 1); ++i; }
    const int J = (i >> 1) + rem;
    const int rowStart = i << 7;
    const int colStart = J << 8;

    // ---- wait until the 6 needed 64-row chunks are normalized ----
    if (tid < 6) {
        const int c = (tid < 4) ? (4 * J + tid) : (2 * i + (tid - 4));
        while (atomicAdd(&g_flag[c], 0) == 0) { }
    }
    __syncthreads();
    __threadfence();

    const int warpM = wid >> 2, warpN = wid & 3;   // 2 x 4 warps, 64x64 each

    const uint32_t sAu = smem_u32(smem);
    const uint32_t sBu = smem_u32(smem + OFF_B);

    const int a_r = lane & 15;
    const int a_k = (lane >> 4) << 3;
    const int b_n = (lane & 7) + ((lane >> 4) << 3);
    const int b_k = ((lane >> 3) & 1) << 3;

    uint32_t hacc[4][8][2];   // f16x2 accumulators (64 regs)
    #pragma unroll
    for (int mi = 0; mi < 4; mi++)
        #pragma unroll
        for (int nj = 0; nj < 8; nj++) { hacc[mi][nj][0] = 0u; hacc[mi][nj][1] = 0u; }

    // ---- prologue: stage 0 ----
    #pragma unroll
    for (int q = 0; q < 4; q++) {
        int idx = tid + q * 256, r = idx >> 3, ch = idx & 7;
        CP_ASYNC16(sAu + (uint32_t)(r * LDS_PAD * 2 + ch * 16),
                   g_h + (size_t)(rowStart + r) * ND + ch * 8);
    }
    #pragma unroll
    for (int q = 0; q < 8; q++) {
        int idx = tid + q * 256, r = idx >> 3, ch = idx & 7;
        CP_ASYNC16(sBu + (uint32_t)(r * LDS_PAD * 2 + ch * 16),
                   g_h + (size_t)(colStart + r) * ND + ch * 8);
    }
    CP_COMMIT();

    for (int kb = 0; kb < KBLOCKS; kb++) {
        CP_WAIT0();
        __syncthreads();

        if (kb + 1 < KBLOCKS) {
            const int k0 = (kb + 1) * BK;
            const uint32_t boA = ((kb + 1) & 1) * A_BUF;
            const uint32_t boB = ((kb + 1) & 1) * B_BUF;
            #pragma unroll
            for (int q = 0; q < 4; q++) {
                int idx = tid + q * 256, r = idx >> 3, ch = idx & 7;
                CP_ASYNC16(sAu + boA + (uint32_t)(r * LDS_PAD * 2 + ch * 16),
                           g_h + (size_t)(rowStart + r) * ND + k0 + ch * 8);
            }
            #pragma unroll
            for (int q = 0; q < 8; q++) {
                int idx = tid + q * 256, r = idx >> 3, ch = idx & 7;
                CP_ASYNC16(sBu + boB + (uint32_t)(r * LDS_PAD * 2 + ch * 16),
                           g_h + (size_t)(colStart + r) * ND + k0 + ch * 8);
            }
            CP_COMMIT();
        }

        const uint32_t boA = (kb & 1) * A_BUF;
        const uint32_t boB = (kb & 1) * B_BUF;
        #pragma unroll
        for (int ks = 0; ks < 4; ks++) {
            uint32_t af[4][4];
            #pragma unroll
            for (int mi = 0; mi < 4; mi++) {
                uint32_t addr = sAu + boA +
                    ((warpM * 64 + mi * 16 + a_r) * LDS_PAD + ks * 16 + a_k) * 2;
                LDMATRIX_X4(af[mi][0], af[mi][1], af[mi][2], af[mi][3], addr);
            }
            uint32_t bf[4][4];
            #pragma unroll
            for (int nb = 0; nb < 4; nb++) {
                uint32_t addr = sBu + boB +
                    ((warpN * 64 + nb * 16 + b_n) * LDS_PAD + ks * 16 + b_k) * 2;
                LDMATRIX_X4(bf[nb][0], bf[nb][1], bf[nb][2], bf[nb][3], addr);
            }
            #pragma unroll
            for (int mi = 0; mi < 4; mi++)
                #pragma unroll
                for (int nj = 0; nj < 8; nj++)
                    MMA16816H(hacc[mi][nj], af[mi],
                              bf[nj >> 1][(nj & 1) * 2], bf[nj >> 1][(nj & 1) * 2 + 1]);
        }
    }

    // ================= epilogue phase 1: row-side top-2 =================
    {
        float2 run[8];
        #pragma unroll
        for (int t2 = 0; t2 < 8; t2++) run[t2] = make_float2(-2.0f, -2.0f);
        #pragma unroll
        for (int mi = 0; mi < 4; mi++) {
            const int row0 = rowStart + warpM * 64 + mi * 16 + (lane >> 2);
            #pragma unroll
            for (int nj = 0; nj < 8; nj++) {
                const int col0 = colStart + warpN * 64 + nj * 8 + (lane & 3) * 2;
                float2 f0 = __half22float2(*reinterpret_cast<__half2*>(&hacc[mi][nj][0]));
                float2 f1 = __half22float2(*reinterpret_cast<__half2*>(&hacc[mi][nj][1]));
                float c0 = f0.x, c1 = f0.y, c2 = f1.x, c3 = f1.y;
                if (col0 < rowStart || col0     == row0)     c0 = -2.0f;
                if (col0 < rowStart || col0 + 1 == row0)     c1 = -2.0f;
                if (col0 < rowStart || col0     == row0 + 8) c2 = -2.0f;
                if (col0 < rowStart || col0 + 1 == row0 + 8) c3 = -2.0f;
                top2_push(run[mi * 2 + 0], c0);
                top2_push(run[mi * 2 + 0], c1);
                top2_push(run[mi * 2 + 1], c2);
                top2_push(run[mi * 2 + 1], c3);
            }
        }
        #pragma unroll
        for (int t2 = 0; t2 < 8; t2++) {
            top2_shfl_merge(run[t2], 1);
            top2_shfl_merge(run[t2], 2);
        }
        __syncthreads();   // A0 scratch safe: every warp past mainloop reads
        if ((lane & 3) == 0) {
            #pragma unroll
            for (int mi = 0; mi < 4; mi++) {
                int rbase = warpM * 64 + mi * 16 + (lane >> 2);
                s_redr[warpN * BM + rbase]     = run[mi * 2 + 0];
                s_redr[warpN * BM + rbase + 8] = run[mi * 2 + 1];
            }
        }
    }

    // ================= epilogue phase 2: col-side top-2 (only c_blk > i) =====
    {
        float2 crun[16];
        #pragma unroll
        for (int t2 = 0; t2 < 16; t2++) crun[t2] = make_float2(-2.0f, -2.0f);
        #pragma unroll
        for (int nj = 0; nj < 8; nj++) {
            const int cblk = (colStart + warpN * 64 + nj * 8) >> 7;
            if (cblk > i) {
                #pragma unroll
                for (int mi = 0; mi < 4; mi++) {
                    float2 f0 = __half22float2(*reinterpret_cast<__half2*>(&hacc[mi][nj][0]));
                    float2 f1 = __half22float2(*reinterpret_cast<__half2*>(&hacc[mi][nj][1]));
                    top2_push(crun[nj * 2 + 0], f0.x);
                    top2_push(crun[nj * 2 + 1], f0.y);
                    top2_push(crun[nj * 2 + 0], f1.x);
                    top2_push(crun[nj * 2 + 1], f1.y);
                }
            }
        }
        #pragma unroll
        for (int t2 = 0; t2 < 16; t2++) {
            top2_shfl_merge(crun[t2], 4);
            top2_shfl_merge(crun[t2], 8);
            top2_shfl_merge(crun[t2], 16);
        }
        if (lane < 4) {
            #pragma unroll
            for (int nj = 0; nj < 8; nj++) {
                int cbase = warpN * 64 + nj * 8 + lane * 2;
                s_redc[warpM * BN + cbase]     = crun[nj * 2 + 0];
                s_redc[warpM * BN + cbase + 1] = crun[nj * 2 + 1];
            }
        }
    }
    __syncthreads();

    if (tid < BM) {
        float2 m = s_redr[tid];
        top2_merge(m, s_redr[BM + tid]);
        top2_merge(m, s_redr[2 * BM + tid]);
        top2_merge(m, s_redr[3 * BM + tid]);
        g_part[(size_t)J * NB + rowStart + tid] = m;
    }
    {
        float2 m = s_redc[tid];
        top2_merge(m, s_redc[BN + tid]);
        g_part[(size_t)(32 + i) * NB + colStart + tid] = m;
    }
}

// ---------------------------------------------------------------------------
// Kernel 2: per-row merge + loss/gate sums, fused last-block finalize;
//           resets flags for next graph replay.
// ---------------------------------------------------------------------------
__global__ void __launch_bounds__(256) loss_kernel(float* __restrict__ out) {
    if (blockIdx.x == 0 && threadIdx.x < NCHUNK) g_flag[threadIdx.x] = 0;

    const int r = blockIdx.x * 256 + threadIdx.x;
    const int b = r >> 7;

    float2 m = make_float2(-2.0f, -2.0f);
    for (int Jx = b >> 1; Jx < NSUPER; Jx++) top2_merge(m, g_part[(size_t)Jx * NB + r]);
    const int imax = b | 1;
    for (int ix = 0; ix <= imax; ix++) top2_merge(m, g_part[(size_t)(32 + ix) * NB + r]);

    float sum_lg = 0.0f, sum_g = 0.0f;
    float d2[2] = {m.x, m.y};
    #pragma unroll
    for (int e = 0; e < 2; e++) {
        float dist = sqrtf(fmaxf(2.0f - 2.0f * d2[e], 0.0f));
        float loss = -logf(dist + 1e-8f);
        float g    = 1.0f / (1.0f + expf(-(loss - 0.5f) * 10.0f));
        sum_lg += loss * g;
        sum_g  += g;
    }
    #pragma unroll
    for (int o = 16; o > 0; o >>= 1) {
        sum_lg += __shfl_xor_sync(0xFFFFFFFFu, sum_lg, o);
        sum_g  += __shfl_xor_sync(0xFFFFFFFFu, sum_g,  o);
    }
    __shared__ float s_lg[8], s_g[8];
    __shared__ bool isLast;
    int lane = threadIdx.x & 31, w = threadIdx.x >> 5;
    if (lane == 0) { s_lg[w] = sum_lg; s_g[w] = sum_g; }
    __syncthreads();
    if (threadIdx.x == 0) {
        float tl = 0.0f, tg = 0.0f;
        #pragma unroll
        for (int q = 0; q < 8; q++) { tl += s_lg[q]; tg += s_g[q]; }
        g_red[blockIdx.x] = make_float2(tl, tg);
        __threadfence();
        int prev = atomicAdd(&g_ctr, 1);
        isLast = (prev == RED_BLOCKS - 1);
    }
    __syncthreads();

    if (isLast && threadIdx.x < 32) {
        float2 p = g_red[threadIdx.x];
        float tl = p.x, tg = p.y;
        #pragma unroll
        for (int o = 16; o > 0; o >>= 1) {
            tl += __shfl_xor_sync(0xFFFFFFFFu, tl, o);
            tg += __shfl_xor_sync(0xFFFFFFFFu, tg, o);
        }
        if (threadIdx.x == 0) {
            float weighted_mean = tl / (float)(NB * 2);
            float gated_mean    = tl / fmaxf(tg, 1.0f);
            out[0] = 0.5f * weighted_mean + 0.5f * gated_mean;
            g_ctr = 0;   // reset for next graph replay (deterministic)
        }
    }
}

// ---------------------------------------------------------------------------
extern "C" void kernel_launch(void* const* d_in, const int* in_sizes, int n_in,
                              void* d_out, int out_size) {
    const float* x = (const float*)d_in[0];
    float* out = (float*)d_out;

    cudaFuncSetAttribute(top2_sym_kernel,
                         cudaFuncAttributeMaxDynamicSharedMemorySize, SMEM_TOTAL);

    top2_sym_kernel<<<NCTAS, THREADS, SMEM_TOTAL>>>(x);
    loss_kernel<<<RED_BLOCKS, 256>>>(out);
}

// round 16
// speedup vs baseline: 1.0300x; 1.0300x over previous
#include <cuda_runtime.h>
#include <cuda_fp16.h>
#include <cstdint>
#include <math.h>

#define NB 8192
#define ND 1024
#define BM 128                  /* CTA rows */
#define BN 256                  /* CTA cols (2 x 128-col blocks) */
#define BK 64
#define NBLK 64                 /* 128-row blocks */
#define NSUPER 32               /* 256-col superblocks */
#define NCTAS 1056              /* sum_{i=0}^{63} (32 - i/2) */
#define THREADS 256
#define LDS_PAD 72              /* halves per smem row (144B) */
#define KBLOCKS (ND / BK)       /* 16 */
#define RED_BLOCKS 128          /* loss kernel blocks (4 threads per row) */

/* dynamic SMEM layout (bytes) */
#define A_BUF 18432             /* 128*144 */
#define B_BUF 36864             /* 256*144 */
#define OFF_B (2 * A_BUF)       /* 36864 */
#define SMEM_TOTAL (OFF_B + 2 * B_BUF)   /* 110592 */
/* epilogue scratch aliases A stage-0 (dead after kb=14) */
#define OFF_RR 0                /* s_redr [4][128] float2 = 4096 B */
#define OFF_RC 4096             /* s_redc [2][256] float2 = 4096 B */

// ---------------- static device scratch (no allocation) --------------------
__device__ __half g_h[NB * ND];             // normalized rows fp16 (16 MB)
__device__ float2 g_part[96 * NB];          // [slot][row]; 0..31 row-side (J), 32..95 col-side (i)
__device__ float2 g_red[RED_BLOCKS];
__device__ int    g_ctr;                    // static-zero; reset in-kernel each run

// ---------------- PTX helpers ----------------------------------------------
__device__ __forceinline__ uint32_t smem_u32(const void* p) {
    uint32_t a;
    asm("{ .reg .u64 t; cvta.to.shared.u64 t, %1; cvt.u32.u64 %0, t; }" : "=r"(a) : "l"(p));
    return a;
}
#define CP_ASYNC16(sm, gp) \
    asm volatile("cp.async.cg.shared.global [%0], [%1], 16;" :: "r"(sm), "l"(gp))
#define CP_COMMIT() asm volatile("cp.async.commit_group;" ::: "memory")
#define CP_WAIT0()  asm volatile("cp.async.wait_group 0;" ::: "memory")
#define LDMATRIX_X4(r0, r1, r2, r3, addr) \
    asm volatile("ldmatrix.sync.aligned.m8n8.x4.shared.b16 {%0,%1,%2,%3}, [%4];" \
                 : "=r"(r0), "=r"(r1), "=r"(r2), "=r"(r3) : "r"(addr))
#define MMA16816H(c, a, b0, b1) \
    asm volatile("mma.sync.aligned.m16n8k16.row.col.f16.f16.f16.f16 " \
                 "{%0,%1},{%2,%3,%4,%5},{%6,%7},{%0,%1};" \
                 : "+r"((c)[0]), "+r"((c)[1]) \
                 : "r"((a)[0]), "r"((a)[1]), "r"((a)[2]), "r"((a)[3]), "r"(b0), "r"(b1))

__device__ __forceinline__ void top2_merge(float2& t, float2 q) {
    if (q.x > t.x) { t.y = fmaxf(t.x, q.y); t.x = q.x; }
    else           { t.y = fmaxf(t.y, q.x); }
}
__device__ __forceinline__ void top2_push(float2& t, float v) {
    if (v > t.x) { t.y = t.x; t.x = v; }
    else if (v > t.y) { t.y = v; }
}
__device__ __forceinline__ void top2_shfl_merge(float2& t, int off) {
    float2 q;
    q.x = __shfl_xor_sync(0xFFFFFFFFu, t.x, off);
    q.y = __shfl_xor_sync(0xFFFFFFFFu, t.y, off);
    top2_merge(t, q);
}

// ---------------------------------------------------------------------------
// Kernel 1: L2-normalize — one warp per row, shuffle-only reduction.
// ---------------------------------------------------------------------------
__global__ void __launch_bounds__(256) normalize_kernel(const float* __restrict__ x) {
    const int warp = threadIdx.x >> 5, lane = threadIdx.x & 31;
    const int row = blockIdx.x * 8 + warp;
    const float4* xr = reinterpret_cast<const float4*>(x + (size_t)row * ND);

    float4 v[8];
    float s = 0.0f;
    #pragma unroll
    for (int q = 0; q < 8; q++) {
        v[q] = xr[lane + 32 * q];
        s += v[q].x * v[q].x + v[q].y * v[q].y + v[q].z * v[q].z + v[q].w * v[q].w;
    }
    #pragma unroll
    for (int o = 16; o > 0; o >>= 1) s += __shfl_xor_sync(0xFFFFFFFFu, s, o);
    const float inv = 1.0f / fmaxf(sqrtf(s), 1e-8f);

    uint2* oh = reinterpret_cast<uint2*>(g_h + (size_t)row * ND);
    #pragma unroll
    for (int q = 0; q < 8; q++) {
        __half2 h0 = __floats2half2_rn(v[q].x * inv, v[q].y * inv);
        __half2 h1 = __floats2half2_rn(v[q].z * inv, v[q].w * inv);
        uint2 pk;
        pk.x = *reinterpret_cast<uint32_t*>(&h0);
        pk.y = *reinterpret_cast<uint32_t*>(&h1);
        oh[lane + 32 * q] = pk;
    }
}

// ---------------------------------------------------------------------------
// Kernel 2: symmetric fp16 mma.sync, f16 accumulators — 128x256 tile per CTA,
//           64x64 warp tiles, BK=64, single sync per k-block.  (UNCHANGED)
// ---------------------------------------------------------------------------
__global__ void __launch_bounds__(THREADS, 2) top2_sym_kernel() {
    extern __shared__ char smem[];
    float2* s_redr = reinterpret_cast<float2*>(smem + OFF_RR);  // [4][128]
    float2* s_redc = reinterpret_cast<float2*>(smem + OFF_RC);  // [2][256]

    // decode (i, J): J >= i/2
    int i = 0, rem = blockIdx.x;
    while (rem >= NSUPER - (i >> 1)) { rem -= NSUPER - (i >> 1); ++i; }
    const int J = (i >> 1) + rem;
    const int rowStart = i << 7;
    const int colStart = J << 8;

    const int tid = threadIdx.x;
    const int wid = tid >> 5, lane = tid & 31;
    const int warpM = wid >> 2, warpN = wid & 3;   // 2 x 4 warps, 64x64 each

    const uint32_t sAu = smem_u32(smem);
    const uint32_t sBu = smem_u32(smem + OFF_B);

    const int a_r = lane & 15;
    const int a_k = (lane >> 4) << 3;
    const int b_n = (lane & 7) + ((lane >> 4) << 3);
    const int b_k = ((lane >> 3) & 1) << 3;

    uint32_t hacc[4][8][2];   // f16x2 accumulators (64 regs)
    #pragma unroll
    for (int mi = 0; mi < 4; mi++)
        #pragma unroll
        for (int nj = 0; nj < 8; nj++) { hacc[mi][nj][0] = 0u; hacc[mi][nj][1] = 0u; }

    // ---- prologue: stage 0 ----
    #pragma unroll
    for (int q = 0; q < 4; q++) {
        int idx = tid + q * 256, r = idx >> 3, ch = idx & 7;
        CP_ASYNC16(sAu + (uint32_t)(r * LDS_PAD * 2 + ch * 16),
                   g_h + (size_t)(rowStart + r) * ND + ch * 8);
    }
    #pragma unroll
    for (int q = 0; q < 8; q++) {
        int idx = tid + q * 256, r = idx >> 3, ch = idx & 7;
        CP_ASYNC16(sBu + (uint32_t)(r * LDS_PAD * 2 + ch * 16),
                   g_h + (size_t)(colStart + r) * ND + ch * 8);
    }
    CP_COMMIT();

    for (int kb = 0; kb < KBLOCKS; kb++) {
        CP_WAIT0();
        __syncthreads();

        if (kb + 1 < KBLOCKS) {
            const int k0 = (kb + 1) * BK;
            const uint32_t boA = ((kb + 1) & 1) * A_BUF;
            const uint32_t boB = ((kb + 1) & 1) * B_BUF;
            #pragma unroll
            for (int q = 0; q < 4; q++) {
                int idx = tid + q * 256, r = idx >> 3, ch = idx & 7;
                CP_ASYNC16(sAu + boA + (uint32_t)(r * LDS_PAD * 2 + ch * 16),
                           g_h + (size_t)(rowStart + r) * ND + k0 + ch * 8);
            }
            #pragma unroll
            for (int q = 0; q < 8; q++) {
                int idx = tid + q * 256, r = idx >> 3, ch = idx & 7;
                CP_ASYNC16(sBu + boB + (uint32_t)(r * LDS_PAD * 2 + ch * 16),
                           g_h + (size_t)(colStart + r) * ND + k0 + ch * 8);
            }
            CP_COMMIT();
        }

        const uint32_t boA = (kb & 1) * A_BUF;
        const uint32_t boB = (kb & 1) * B_BUF;
        #pragma unroll
        for (int ks = 0; ks < 4; ks++) {
            uint32_t af[4][4];
            #pragma unroll
            for (int mi = 0; mi < 4; mi++) {
                uint32_t addr = sAu + boA +
                    ((warpM * 64 + mi * 16 + a_r) * LDS_PAD + ks * 16 + a_k) * 2;
                LDMATRIX_X4(af[mi][0], af[mi][1], af[mi][2], af[mi][3], addr);
            }
            uint32_t bf[4][4];
            #pragma unroll
            for (int nb = 0; nb < 4; nb++) {
                uint32_t addr = sBu + boB +
                    ((warpN * 64 + nb * 16 + b_n) * LDS_PAD + ks * 16 + b_k) * 2;
                LDMATRIX_X4(bf[nb][0], bf[nb][1], bf[nb][2], bf[nb][3], addr);
            }
            #pragma unroll
            for (int mi = 0; mi < 4; mi++)
                #pragma unroll
                for (int nj = 0; nj < 8; nj++)
                    MMA16816H(hacc[mi][nj], af[mi],
                              bf[nj >> 1][(nj & 1) * 2], bf[nj >> 1][(nj & 1) * 2 + 1]);
        }
    }

    // ================= epilogue phase 1: row-side top-2 =================
    {
        float2 run[8];
        #pragma unroll
        for (int t2 = 0; t2 < 8; t2++) run[t2] = make_float2(-2.0f, -2.0f);
        #pragma unroll
        for (int mi = 0; mi < 4; mi++) {
            const int row0 = rowStart + warpM * 64 + mi * 16 + (lane >> 2);
            #pragma unroll
            for (int nj = 0; nj < 8; nj++) {
                const int col0 = colStart + warpN * 64 + nj * 8 + (lane & 3) * 2;
                float2 f0 = __half22float2(*reinterpret_cast<__half2*>(&hacc[mi][nj][0]));
                float2 f1 = __half22float2(*reinterpret_cast<__half2*>(&hacc[mi][nj][1]));
                float c0 = f0.x, c1 = f0.y, c2 = f1.x, c3 = f1.y;
                if (col0 < rowStart || col0     == row0)     c0 = -2.0f;
                if (col0 < rowStart || col0 + 1 == row0)     c1 = -2.0f;
                if (col0 < rowStart || col0     == row0 + 8) c2 = -2.0f;
                if (col0 < rowStart || col0 + 1 == row0 + 8) c3 = -2.0f;
                top2_push(run[mi * 2 + 0], c0);
                top2_push(run[mi * 2 + 0], c1);
                top2_push(run[mi * 2 + 1], c2);
                top2_push(run[mi * 2 + 1], c3);
            }
        }
        #pragma unroll
        for (int t2 = 0; t2 < 8; t2++) {
            top2_shfl_merge(run[t2], 1);
            top2_shfl_merge(run[t2], 2);
        }
        __syncthreads();   // A0 scratch safe: every warp past mainloop reads
        if ((lane & 3) == 0) {
            #pragma unroll
            for (int mi = 0; mi < 4; mi++) {
                int rbase = warpM * 64 + mi * 16 + (lane >> 2);
                s_redr[warpN * BM + rbase]     = run[mi * 2 + 0];
                s_redr[warpN * BM + rbase + 8] = run[mi * 2 + 1];
            }
        }
    }

    // ================= epilogue phase 2: col-side top-2 (only c_blk > i) =====
    {
        float2 crun[16];
        #pragma unroll
        for (int t2 = 0; t2 < 16; t2++) crun[t2] = make_float2(-2.0f, -2.0f);
        #pragma unroll
        for (int nj = 0; nj < 8; nj++) {
            const int cblk = (colStart + warpN * 64 + nj * 8) >> 7;
            if (cblk > i) {
                #pragma unroll
                for (int mi = 0; mi < 4; mi++) {
                    float2 f0 = __half22float2(*reinterpret_cast<__half2*>(&hacc[mi][nj][0]));
                    float2 f1 = __half22float2(*reinterpret_cast<__half2*>(&hacc[mi][nj][1]));
                    top2_push(crun[nj * 2 + 0], f0.x);
                    top2_push(crun[nj * 2 + 1], f0.y);
                    top2_push(crun[nj * 2 + 0], f1.x);
                    top2_push(crun[nj * 2 + 1], f1.y);
                }
            }
        }
        #pragma unroll
        for (int t2 = 0; t2 < 16; t2++) {
            top2_shfl_merge(crun[t2], 4);
            top2_shfl_merge(crun[t2], 8);
            top2_shfl_merge(crun[t2], 16);
        }
        if (lane < 4) {
            #pragma unroll
            for (int nj = 0; nj < 8; nj++) {
                int cbase = warpN * 64 + nj * 8 + lane * 2;
                s_redc[warpM * BN + cbase]     = crun[nj * 2 + 0];
                s_redc[warpM * BN + cbase + 1] = crun[nj * 2 + 1];
            }
        }
    }
    __syncthreads();

    if (tid < BM) {
        float2 m = s_redr[tid];
        top2_merge(m, s_redr[BM + tid]);
        top2_merge(m, s_redr[2 * BM + tid]);
        top2_merge(m, s_redr[3 * BM + tid]);
        g_part[(size_t)J * NB + rowStart + tid] = m;
    }
    {
        float2 m = s_redc[tid];
        top2_merge(m, s_redc[BN + tid]);
        g_part[(size_t)(32 + i) * NB + colStart + tid] = m;
    }
}

// ---------------------------------------------------------------------------
// Kernel 3: per-row merge (4 threads/row) + loss/gate sums + last-block final
// ---------------------------------------------------------------------------
__global__ void __launch_bounds__(256) loss_kernel(float* __restrict__ out) {
    const int gidx = blockIdx.x * 256 + threadIdx.x;
    const int r = gidx >> 2;          // row
    const int sub = gidx & 3;         // quarter of this row's slots
    const int b = r >> 7;             // 128-row block

    const int nrow = NSUPER - (b >> 1);       // row-side slots: J = b/2 .. 31
    const int ncol = (b | 1) + 1;             // col-side slots: i = 0 .. b|1
    const int total = nrow + ncol;

    float2 m = make_float2(-2.0f, -2.0f);
    for (int t = sub; t < total; t += 4) {
        const int slot = (t < nrow) ? ((b >> 1) + t) : (32 + (t - nrow));
        top2_merge(m, g_part[(size_t)slot * NB + r]);
    }
    // merge the 4 subs (lanes of a quad hold the same row)
    top2_shfl_merge(m, 1);
    top2_shfl_merge(m, 2);

    float sum_lg = 0.0f, sum_g = 0.0f;
    if (sub == 0) {
        float d2[2] = {m.x, m.y};
        #pragma unroll
        for (int e = 0; e < 2; e++) {
            float dist = sqrtf(fmaxf(2.0f - 2.0f * d2[e], 0.0f));
            float loss = -logf(dist + 1e-8f);
            float g    = 1.0f / (1.0f + expf(-(loss - 0.5f) * 10.0f));
            sum_lg += loss * g;
            sum_g  += g;
        }
    }
    #pragma unroll
    for (int o = 16; o > 0; o >>= 1) {
        sum_lg += __shfl_xor_sync(0xFFFFFFFFu, sum_lg, o);
        sum_g  += __shfl_xor_sync(0xFFFFFFFFu, sum_g,  o);
    }
    __shared__ float s_lg[8], s_g[8];
    __shared__ bool isLast;
    int lane = threadIdx.x & 31, w = threadIdx.x >> 5;
    if (lane == 0) { s_lg[w] = sum_lg; s_g[w] = sum_g; }
    __syncthreads();
    if (threadIdx.x == 0) {
        float tl = 0.0f, tg = 0.0f;
        #pragma unroll
        for (int q = 0; q < 8; q++) { tl += s_lg[q]; tg += s_g[q]; }
        g_red[blockIdx.x] = make_float2(tl, tg);
        __threadfence();
        int prev = atomicAdd(&g_ctr, 1);
        isLast = (prev == RED_BLOCKS - 1);
    }
    __syncthreads();

    if (isLast) {
        float tl = 0.0f, tg = 0.0f;
        if (threadIdx.x < RED_BLOCKS) {
            float2 p = g_red[threadIdx.x];
            tl = p.x; tg = p.y;
        }
        #pragma unroll
        for (int o = 16; o > 0; o >>= 1) {
            tl += __shfl_xor_sync(0xFFFFFFFFu, tl, o);
            tg += __shfl_xor_sync(0xFFFFFFFFu, tg, o);
        }
        if (lane == 0) { s_lg[w] = tl; s_g[w] = tg; }
        __syncthreads();
        if (threadIdx.x == 0) {
            float ftl = 0.0f, ftg = 0.0f;
            #pragma unroll
            for (int q = 0; q < 8; q++) { ftl += s_lg[q]; ftg += s_g[q]; }
            float weighted_mean = ftl / (float)(NB * 2);
            float gated_mean    = ftl / fmaxf(ftg, 1.0f);
            out[0] = 0.5f * weighted_mean + 0.5f * gated_mean;
            g_ctr = 0;   // reset for next graph replay (deterministic)
        }
    }
}

// ---------------------------------------------------------------------------
extern "C" void kernel_launch(void* const* d_in, const int* in_sizes, int n_in,
                              void* d_out, int out_size) {
    const float* x = (const float*)d_in[0];
    float* out = (float*)d_out;

    cudaFuncSetAttribute(top2_sym_kernel,
                         cudaFuncAttributeMaxDynamicSharedMemorySize, SMEM_TOTAL);

    normalize_kernel<<<NB / 8, 256>>>(x);
    top2_sym_kernel<<<NCTAS, THREADS, SMEM_TOTAL>>>();
    loss_kernel<<<RED_BLOCKS, 256>>>(out);
}